// round 1
// baseline (speedup 1.0000x reference)
#include <cuda_runtime.h>
#include <cuda_bf16.h>
#include <math.h>

#define EPS_CLAMP 1e-4f

__device__ float g_M[27];   // M = W3*W2*W1, [9,3] row-major
__device__ float g_C9[81];  // constant additive term, [9,9]

// ---------------------------------------------------------------------------
// Prep: build M and C9 from W1,W2,W3. One small block, staged via smem.
// ---------------------------------------------------------------------------
__global__ void spd_prep_kernel(const float* __restrict__ W1,
                                const float* __restrict__ W2,
                                const float* __restrict__ W3) {
    __shared__ float A1[25];   // I5 - W1 W1^T
    __shared__ float W21[21];  // W2 @ W1   [7,3]
    __shared__ float S7[49];   // W2 A1 W2^T + (I7 - W2 W2^T)
    int t = threadIdx.x;       // 96 threads

    if (t < 25) {
        int i = t / 5, j = t % 5;
        float s = 0.f;
        #pragma unroll
        for (int k = 0; k < 3; k++) s += W1[i*3+k] * W1[j*3+k];
        A1[t] = (i == j ? 1.0f : 0.0f) - s;
    }
    if (t >= 25 && t < 46) {
        int u = t - 25; int i = u / 3, k = u % 3;
        float s = 0.f;
        #pragma unroll
        for (int a = 0; a < 5; a++) s += W2[i*5+a] * W1[a*3+k];
        W21[u] = s;
    }
    __syncthreads();
    if (t < 49) {
        int i = t / 7, j = t % 7;
        float s = 0.f;
        #pragma unroll
        for (int a = 0; a < 5; a++) {
            float ta = 0.f;
            #pragma unroll
            for (int b = 0; b < 5; b++) ta += A1[a*5+b] * W2[j*5+b];
            s += W2[i*5+a] * ta;
        }
        float w2ij = 0.f;
        #pragma unroll
        for (int a = 0; a < 5; a++) w2ij += W2[i*5+a] * W2[j*5+a];
        S7[t] = s + (i == j ? 1.0f : 0.0f) - w2ij;
    }
    if (t >= 49 && t < 76) {
        int u = t - 49; int r = u / 3, k = u % 3;
        float s = 0.f;
        #pragma unroll
        for (int a = 0; a < 7; a++) s += W3[r*7+a] * W21[a*3+k];
        g_M[u] = s;
    }
    __syncthreads();
    if (t < 81) {
        int i = t / 9, j = t % 9;
        float s = 0.f;
        #pragma unroll
        for (int a = 0; a < 7; a++) {
            float ta = 0.f;
            #pragma unroll
            for (int b = 0; b < 7; b++) ta += S7[a*7+b] * W3[j*7+b];
            s += W3[i*7+a] * ta;
        }
        float w3ij = 0.f;
        #pragma unroll
        for (int a = 0; a < 7; a++) w3ij += W3[i*7+a] * W3[j*7+a];
        g_C9[t] = EPS_CLAMP * (s + (i == j ? 1.0f : 0.0f) - w3ij);
    }
}

// ---------------------------------------------------------------------------
// 3x3 Jacobi rotation (compile-time P,Q), updates A and accumulates V.
// ---------------------------------------------------------------------------
template <int P, int Q>
__device__ __forceinline__ void jacobi_rot(float A[3][3], float V[3][3]) {
    float apq = A[P][Q];
    if (fabsf(apq) < 1e-30f) return;
    float app = A[P][P], aqq = A[Q][Q];
    float theta = 0.5f * (aqq - app) / apq;
    float t = copysignf(1.0f, theta) / (fabsf(theta) + sqrtf(theta * theta + 1.0f));
    float c = rsqrtf(t * t + 1.0f);
    float s = t * c;
    A[P][P] = app - t * apq;
    A[Q][Q] = aqq + t * apq;
    A[P][Q] = 0.f; A[Q][P] = 0.f;
    const int R = 3 - P - Q;
    float arp = A[R][P], arq = A[R][Q];
    float nrp = c * arp - s * arq;
    float nrq = s * arp + c * arq;
    A[R][P] = nrp; A[P][R] = nrp;
    A[R][Q] = nrq; A[Q][R] = nrq;
    #pragma unroll
    for (int k = 0; k < 3; k++) {
        float vp = V[k][P], vq = V[k][Q];
        V[k][P] = c * vp - s * vq;
        V[k][Q] = s * vp + c * vq;
    }
}

// ---------------------------------------------------------------------------
// Main kernel: one thread per batch element; smem staging for coalesced I/O.
// ---------------------------------------------------------------------------
#define BLK 128

__global__ void __launch_bounds__(BLK)
spd_main_kernel(const float* __restrict__ vech, float* __restrict__ out, int B) {
    __shared__ float sM[27];
    __shared__ float sC[81];
    __shared__ float stage[BLK * 81];  // 41472 B

    const int tid = threadIdx.x;
    const int item0 = blockIdx.x * BLK;
    const int nItems = min(BLK, B - item0);

    if (tid < 27) sM[tid] = g_M[tid];
    if (tid < 81) sC[tid] = g_C9[tid];

    // Stage vech reads coalesced
    const int nflt = nItems * 6;
    for (int idx = tid; idx < nflt; idx += BLK)
        stage[idx] = vech[(size_t)item0 * 6 + idx];
    __syncthreads();

    float v[6];
    const bool active = tid < nItems;
    if (active) {
        #pragma unroll
        for (int k = 0; k < 6; k++) v[k] = stage[tid * 6 + k];
    }
    __syncthreads();  // done reading stage; will be overwritten with outputs

    if (active) {
        // Build symmetric A from vech (triu order 00,01,02,11,12,22)
        float A[3][3] = {{v[0], v[1], v[2]},
                         {v[1], v[3], v[4]},
                         {v[2], v[4], v[5]}};
        float V[3][3] = {{1, 0, 0}, {0, 1, 0}, {0, 0, 1}};

        #pragma unroll
        for (int sweep = 0; sweep < 5; sweep++) {
            jacobi_rot<0, 1>(A, V);
            jacobi_rot<0, 2>(A, V);
            jacobi_rot<1, 2>(A, V);
        }
        float e0 = expf(A[0][0]);
        float e1 = expf(A[1][1]);
        float e2 = expf(A[2][2]);

        // X3 = V diag(e) V^T  (symmetric 3x3)
        float x[3][3];
        #pragma unroll
        for (int i = 0; i < 3; i++) {
            #pragma unroll
            for (int j = i; j < 3; j++) {
                float s = V[i][0] * e0 * V[j][0]
                        + V[i][1] * e1 * V[j][1]
                        + V[i][2] * e2 * V[j][2];
                x[i][j] = s; x[j][i] = s;
            }
        }

        // Y = M * X3   [9,3]
        float Y[9][3];
        #pragma unroll
        for (int r = 0; r < 9; r++) {
            float m0 = sM[r*3+0], m1 = sM[r*3+1], m2 = sM[r*3+2];
            #pragma unroll
            for (int k = 0; k < 3; k++)
                Y[r][k] = m0 * x[0][k] + m1 * x[1][k] + m2 * x[2][k];
        }

        // X9 = Y * M^T + C9 (symmetric) -> stage[tid*81 + ...]
        float* st = &stage[tid * 81];
        #pragma unroll
        for (int r = 0; r < 9; r++) {
            #pragma unroll
            for (int c = r; c < 9; c++) {
                float val = Y[r][0] * sM[c*3+0]
                          + Y[r][1] * sM[c*3+1]
                          + Y[r][2] * sM[c*3+2]
                          + sC[r*9+c];
                st[r*9+c] = val;
                st[c*9+r] = val;
            }
        }
    }
    __syncthreads();

    // Coalesced block-contiguous store
    if (nItems == BLK) {
        float4* o4 = reinterpret_cast<float4*>(out + (size_t)item0 * 81);
        const float4* s4 = reinterpret_cast<const float4*>(stage);
        #pragma unroll 4
        for (int idx = tid; idx < (BLK * 81) / 4; idx += BLK)
            o4[idx] = s4[idx];
    } else {
        const int nOut = nItems * 81;
        for (int idx = tid; idx < nOut; idx += BLK)
            out[(size_t)item0 * 81 + idx] = stage[idx];
    }
}

// ---------------------------------------------------------------------------
extern "C" void kernel_launch(void* const* d_in, const int* in_sizes, int n_in,
                              void* d_out, int out_size) {
    // Identify inputs by element count for robustness:
    // vech = B*6 (largest), W1 = 15, W2 = 35, W3 = 63.
    const float* vech = nullptr;
    const float* W1 = nullptr;
    const float* W2 = nullptr;
    const float* W3 = nullptr;
    int vech_elems = 0;
    for (int i = 0; i < n_in; i++) {
        int sz = in_sizes[i];
        if (sz == 15)      W1 = (const float*)d_in[i];
        else if (sz == 35) W2 = (const float*)d_in[i];
        else if (sz == 63) W3 = (const float*)d_in[i];
        else { vech = (const float*)d_in[i]; vech_elems = sz; }
    }
    int B = vech_elems / 6;

    spd_prep_kernel<<<1, 96>>>(W1, W2, W3);
    int grid = (B + BLK - 1) / BLK;
    spd_main_kernel<<<grid, BLK>>>(vech, (float*)d_out, B);
}

// round 3
// speedup vs baseline: 1.4067x; 1.4067x over previous
#include <cuda_runtime.h>
#include <cuda_bf16.h>
#include <math.h>

#define EPS_CLAMP 1e-4f
#define BLK 128

// ---------------------------------------------------------------------------
// Main kernel: one thread per batch element.
//  - Per-block prep: build M = W3 W2 W1 [9x3] and C9 [9x9] in smem (~100 flops).
//  - Per-thread: analytic eigenvalues of symmetric 3x3, exp(A) via Newton
//    divided differences (alpha*A^2 + beta*A + gamma*I) -- NO eigenvectors.
//  - Symmetric congruence to 9x9, staged in smem, coalesced float4 stores.
// ---------------------------------------------------------------------------
__global__ void __launch_bounds__(BLK)
spd_main_kernel(const float* __restrict__ vech,
                const float* __restrict__ W1,
                const float* __restrict__ W2,
                const float* __restrict__ W3,
                float* __restrict__ out, int B) {
    // stage FIRST and 16B-aligned: it is reinterpreted as float4.
    __shared__ __align__(16) float stage[BLK * 81];
    __shared__ float A1[25];   // I5 - W1 W1^T
    __shared__ float W21[21];  // W2 @ W1 [7,3]
    __shared__ float S7[49];   // W2 A1 W2^T + (I7 - W2 W2^T)
    __shared__ float sM[27];   // M = W3 W2 W1 [9,3]
    __shared__ float sC[81];   // EPS * (W3 S7 W3^T + I9 - W3 W3^T)

    const int t = threadIdx.x;
    const int item0 = blockIdx.x * BLK;
    const int nItems = min(BLK, B - item0);

    // Stage vech reads (issue global loads early)
    {
        const int nflt = nItems * 6;
        for (int idx = t; idx < nflt; idx += BLK)
            stage[idx] = vech[(size_t)item0 * 6 + idx];
    }

    // ---- prep phase 0 ----
    if (t < 25) {
        int i = t / 5, j = t % 5;
        float s = 0.f;
        #pragma unroll
        for (int k = 0; k < 3; k++) s += W1[i*3+k] * W1[j*3+k];
        A1[t] = (i == j ? 1.0f : 0.0f) - s;
    } else if (t < 46) {
        int u = t - 25; int i = u / 3, k = u % 3;
        float s = 0.f;
        #pragma unroll
        for (int a = 0; a < 5; a++) s += W2[i*5+a] * W1[a*3+k];
        W21[u] = s;
    }
    __syncthreads();

    // ---- prep phase 1 ----
    if (t < 49) {
        int i = t / 7, j = t % 7;
        float s = 0.f;
        #pragma unroll
        for (int a = 0; a < 5; a++) {
            float ta = 0.f;
            #pragma unroll
            for (int b = 0; b < 5; b++) ta += A1[a*5+b] * W2[j*5+b];
            s += W2[i*5+a] * ta;
        }
        float w2ij = 0.f;
        #pragma unroll
        for (int a = 0; a < 5; a++) w2ij += W2[i*5+a] * W2[j*5+a];
        S7[t] = s + (i == j ? 1.0f : 0.0f) - w2ij;
    } else if (t < 76) {
        int u = t - 49; int r = u / 3, k = u % 3;
        float s = 0.f;
        #pragma unroll
        for (int a = 0; a < 7; a++) s += W3[r*7+a] * W21[a*3+k];
        sM[u] = s;
    }
    __syncthreads();

    // ---- prep phase 2 (needs S7) + read vech from stage ----
    if (t < 81) {
        int i = t / 9, j = t % 9;
        float s = 0.f;
        #pragma unroll
        for (int a = 0; a < 7; a++) {
            float ta = 0.f;
            #pragma unroll
            for (int b = 0; b < 7; b++) ta += S7[a*7+b] * W3[j*7+b];
            s += W3[i*7+a] * ta;
        }
        float w3ij = 0.f;
        #pragma unroll
        for (int a = 0; a < 7; a++) w3ij += W3[i*7+a] * W3[j*7+a];
        sC[t] = EPS_CLAMP * (s + (i == j ? 1.0f : 0.0f) - w3ij);
    }

    float v[6];
    const bool active = t < nItems;
    if (active) {
        #pragma unroll
        for (int k = 0; k < 6; k++) v[k] = stage[t * 6 + k];
    }
    __syncthreads();  // sC ready; stage reads done -> stage free for output

    if (active) {
        const float a00 = v[0], a01 = v[1], a02 = v[2];
        const float a11 = v[3], a12 = v[4], a22 = v[5];

        // ---- analytic eigenvalues (trig method), sorted l0 >= l1 >= l2 ----
        const float q   = (a00 + a11 + a22) * (1.0f / 3.0f);
        const float b00 = a00 - q, b11 = a11 - q, b22 = a22 - q;
        const float off2 = a01*a01 + a02*a02 + a12*a12;
        const float p2_half = 0.5f * (b00*b00 + b11*b11 + b22*b22) + off2; // tr(B^2)/2
        const float pp = sqrtf(p2_half * (1.0f / 3.0f));                   // sqrt(tr(B^2)/6)
        const float detB = b00 * (b11*b22 - a12*a12)
                         - a01 * (a01*b22 - a12*a02)
                         + a02 * (a01*a12 - b11*a02);
        const float pinv = __fdividef(1.0f, fmaxf(pp, 1e-30f));
        float r = 0.5f * detB * pinv * pinv * pinv;
        r = fminf(1.0f, fmaxf(-1.0f, r));
        const float phi = acosf(r) * (1.0f / 3.0f);            // in [0, pi/3]
        const float l0 = q + 2.0f * pp * __cosf(phi);          // largest
        const float l2 = q + 2.0f * pp * __cosf(phi + 2.0943951023931953f); // smallest
        const float l1 = 3.0f * q - l0 - l2;

        // ---- exp via Newton divided differences (stable via expm1) ----
        const float d01 = l0 - l1, d12 = l1 - l2, d02 = l0 - l2;  // all >= 0
        const float e2  = __expf(l2);
        const float g12 = expm1f(d12);
        const float e1  = e2 * (g12 + 1.0f);
        const float f12 = (d12 > 1e-10f) ? e2 * __fdividef(g12, d12) : e2;
        const float g01 = expm1f(d01);
        const float e0  = e1 * (g01 + 1.0f);
        const float f01 = (d01 > 1e-10f) ? e1 * __fdividef(g01, d01) : e1;
        const float f012 = (d02 > 1e-10f) ? __fdividef(f01 - f12, d02) : 0.5f * e1;

        // exp(A) = alpha*A^2 + beta*A + gamma*I
        const float alpha = f012;
        const float beta  = f01 - f012 * (l0 + l1);
        const float gamma = e0 - f01 * l0 + f012 * (l0 * l1);

        // A^2 (symmetric)
        const float s00 = a00*a00 + a01*a01 + a02*a02;
        const float s01 = a00*a01 + a01*a11 + a02*a12;
        const float s02 = a00*a02 + a01*a12 + a02*a22;
        const float s11 = a01*a01 + a11*a11 + a12*a12;
        const float s12 = a01*a02 + a11*a12 + a12*a22;
        const float s22 = a02*a02 + a12*a12 + a22*a22;

        float x[3][3];
        x[0][0] = alpha*s00 + beta*a00 + gamma;
        x[0][1] = alpha*s01 + beta*a01;         x[1][0] = x[0][1];
        x[0][2] = alpha*s02 + beta*a02;         x[2][0] = x[0][2];
        x[1][1] = alpha*s11 + beta*a11 + gamma;
        x[1][2] = alpha*s12 + beta*a12;         x[2][1] = x[1][2];
        x[2][2] = alpha*s22 + beta*a22 + gamma;

        // Y = M * X3   [9,3]
        float Y[9][3];
        #pragma unroll
        for (int rr = 0; rr < 9; rr++) {
            const float m0 = sM[rr*3+0], m1 = sM[rr*3+1], m2 = sM[rr*3+2];
            #pragma unroll
            for (int k = 0; k < 3; k++)
                Y[rr][k] = m0 * x[0][k] + m1 * x[1][k] + m2 * x[2][k];
        }

        // X9 = Y * M^T + C9 (symmetric) -> stage
        float* st = &stage[t * 81];
        #pragma unroll
        for (int rr = 0; rr < 9; rr++) {
            #pragma unroll
            for (int cc = rr; cc < 9; cc++) {
                const float val = Y[rr][0] * sM[cc*3+0]
                                + Y[rr][1] * sM[cc*3+1]
                                + Y[rr][2] * sM[cc*3+2]
                                + sC[rr*9+cc];
                st[rr*9+cc] = val;
                st[cc*9+rr] = val;
            }
        }
    }
    __syncthreads();

    // Coalesced block-contiguous store
    if (nItems == BLK) {
        float4* o4 = reinterpret_cast<float4*>(out + (size_t)item0 * 81);
        const float4* s4 = reinterpret_cast<const float4*>(stage);
        #pragma unroll 4
        for (int idx = t; idx < (BLK * 81) / 4; idx += BLK)
            o4[idx] = s4[idx];
    } else {
        const int nOut = nItems * 81;
        for (int idx = t; idx < nOut; idx += BLK)
            out[(size_t)item0 * 81 + idx] = stage[idx];
    }
}

// ---------------------------------------------------------------------------
extern "C" void kernel_launch(void* const* d_in, const int* in_sizes, int n_in,
                              void* d_out, int out_size) {
    const float* vech = nullptr;
    const float* W1 = nullptr;
    const float* W2 = nullptr;
    const float* W3 = nullptr;
    int vech_elems = 0;
    for (int i = 0; i < n_in; i++) {
        int sz = in_sizes[i];
        if (sz == 15)      W1 = (const float*)d_in[i];
        else if (sz == 35) W2 = (const float*)d_in[i];
        else if (sz == 63) W3 = (const float*)d_in[i];
        else { vech = (const float*)d_in[i]; vech_elems = sz; }
    }
    int B = vech_elems / 6;
    int grid = (B + BLK - 1) / BLK;
    spd_main_kernel<<<grid, BLK>>>(vech, W1, W2, W3, (float*)d_out, B);
}